// round 5
// baseline (speedup 1.0000x reference)
#include <cuda_runtime.h>
#include <cuda_bf16.h>
#include <math.h>

// ---------------------------------------------------------------------------
// CGCA branch, fully collapsed:
//   gc = adj·fc1·blockdiag(w2)·w1·avg = B·avg   (everything before relu is
//   linear & batch-independent except avg).
// Kernel P: build B[17,512] (one block per row; full-unroll MLP on w1)  ~3us
// Kernel 1: spatial mean x[n,512,56,56] -> g_avg[n,512]  (HBM roofline)
// Kernel 2: per-batch: gc = B·avg, relu, out = sigmoid(fc2·gc)          ~4us
// ---------------------------------------------------------------------------

#define J   17
#define C   512
#define CA  272
#define HW  3136           // 56*56
#define HW4 784            // HW/4
#define NEG (-9e15f)

// flatnonzero(ADJ) — 49 entries
__constant__ int NZ[49] = {
      0,   1,
     17,  18,  19,
     35,  36,  40,
     54,  55,  57,
     71,  72,  73,
     89,  90,
    104, 105, 108, 109,
    125, 126, 127,
    143, 144, 147, 148, 152,
    162, 169,
    180, 181,
    197, 198, 199,
    212, 215, 216,
    229, 234, 235,
    251, 252, 253,
    269, 270,
    280, 281, 288
};

// scratch (static device globals — no allocation)
__device__ float g_avg[256 * C];   // pooled features, max batch 256
__device__ float g_B[J * C];       // collapsed linear map [17, 512]

// ---------------------------------------------------------------------------
// Kernel P: one block per output row j of B. 512 threads.
//   adj row j (softmax of scattered e), F = adj_j · fc1  [272],
//   T = F · blockdiag(w2) [272],  B[j,:] = T · w1  [512].
// The final accumulation is FULLY unrolled so ptxas front-batches ~50 LDGs
// (MLP ~50 vs 4 before) — kills the DRAM-latency serial chain.
// ---------------------------------------------------------------------------
__global__ __launch_bounds__(512) void precompute_B_kernel(
    const float* __restrict__ e,     // [49]
    const float* __restrict__ fc1,   // [J, CA]
    const float* __restrict__ w2,    // [CA, J]  (== blockdiag groups [16,J,J])
    const float* __restrict__ w1,    // [CA, C]
    float* __restrict__ B)           // [J, C]
{
    __shared__ float adjs[J * J];
    __shared__ float arow[J];
    __shared__ float F[CA];
    __shared__ float T[CA];

    const int j = blockIdx.x;
    const int t = threadIdx.x;

    if (t < J * J) adjs[t] = NEG;
    __syncthreads();
    if (t < 49) adjs[NZ[t]] = e[t];
    __syncthreads();

    if (t == 0) {
        float m = NEG;
#pragma unroll
        for (int k = 0; k < J; k++) m = fmaxf(m, adjs[j * J + k]);
        float s = 0.f, tmp[J];
#pragma unroll
        for (int k = 0; k < J; k++) { tmp[k] = expf(adjs[j * J + k] - m); s += tmp[k]; }
        float inv = 1.0f / s;
#pragma unroll
        for (int k = 0; k < J; k++) arow[k] = tmp[k] * inv;
    }
    __syncthreads();

    // F[k] = sum_{j2} arow[j2] * fc1[j2, k]
    if (t < CA) {
        float s = 0.f;
#pragma unroll
        for (int j2 = 0; j2 < J; j2++) s += arow[j2] * fc1[j2 * CA + t];
        F[t] = s;
    }
    __syncthreads();

    // T[g*17+i] = sum_o F[g*17+o] * w2[(g*17+o)*17 + i]
    if (t < CA) {
        int g = t / J, i = t % J;
        float s = 0.f;
#pragma unroll
        for (int o = 0; o < J; o++) s += F[g * J + o] * w2[(g * J + o) * J + i];
        T[t] = s;
    }
    __syncthreads();

    // B[j, c] = sum_k T[k] * w1[k, c]   (c = t, coalesced w1 reads)
    // Split into 4 independent accumulators + FULL unroll: maximizes the
    // number of outstanding LDGs per warp (latency-bound phase).
    {
        float s0 = 0.f, s1 = 0.f, s2 = 0.f, s3 = 0.f;
#pragma unroll
        for (int k = 0; k < CA / 4; k++) {
            s0 += T[4 * k + 0] * w1[(4 * k + 0) * C + t];
            s1 += T[4 * k + 1] * w1[(4 * k + 1) * C + t];
            s2 += T[4 * k + 2] * w1[(4 * k + 2) * C + t];
            s3 += T[4 * k + 3] * w1[(4 * k + 3) * C + t];
        }
        B[j * C + t] = (s0 + s1) + (s2 + s3);
    }
}

// ---------------------------------------------------------------------------
// Kernel 1: one warp per (n, c) row. 784 float4 per row = 24 unrolled vec4
// iterations + 16-lane tail. Streaming loads (zero reuse), shuffle reduce.
// ---------------------------------------------------------------------------
__global__ __launch_bounds__(256) void mean_pool_kernel(
    const float* __restrict__ x, float* __restrict__ avg, int rows)
{
    int warp = (blockIdx.x * blockDim.x + threadIdx.x) >> 5;
    int lane = threadIdx.x & 31;
    if (warp >= rows) return;

    const float4* p = reinterpret_cast<const float4*>(x) + (size_t)warp * HW4;

    float4 a = make_float4(0.f, 0.f, 0.f, 0.f);
#pragma unroll
    for (int i = 0; i < 24; i++) {
        float4 v = __ldcs(&p[lane + i * 32]);
        a.x += v.x; a.y += v.y; a.z += v.z; a.w += v.w;
    }
    if (lane < 16) {                       // 784 - 24*32 = 16 tail vec4s
        float4 v = __ldcs(&p[768 + lane]);
        a.x += v.x; a.y += v.y; a.z += v.z; a.w += v.w;
    }
    float s = (a.x + a.y) + (a.z + a.w);
#pragma unroll
    for (int o = 16; o; o >>= 1) s += __shfl_xor_sync(0xffffffffu, s, o);

    if (lane == 0) avg[warp] = s * (1.0f / (float)HW);
}

// ---------------------------------------------------------------------------
// Kernel 2: one block (544 threads = 17 warps) per batch element.
//   warp j:  gc[j] = relu( dot(B[j,:], avg) )
//   thread c<512: out[c] = sigmoid( dot(gc, fc2[c,:]) )
// ---------------------------------------------------------------------------
__global__ __launch_bounds__(544) void final_kernel(
    const float* __restrict__ B,     // [J, C]
    const float* __restrict__ fc2,   // [C, J]
    float* __restrict__ out)         // [n, C]
{
    __shared__ float avgs[C];
    __shared__ float gcs[J];

    const int b    = blockIdx.x;
    const int t    = threadIdx.x;
    const int wid  = t >> 5;       // 0..16
    const int lane = t & 31;

    if (t < C) avgs[t] = g_avg[b * C + t];
    __syncthreads();

    // 17 warps, one gc each
    {
        const float* wr = B + (size_t)wid * C;
        float s = 0.f;
#pragma unroll
        for (int k = lane; k < C; k += 32) s += avgs[k] * wr[k];
#pragma unroll
        for (int off = 16; off; off >>= 1) s += __shfl_xor_sync(0xffffffffu, s, off);
        if (lane == 0) gcs[wid] = fmaxf(s, 0.f);
    }
    __syncthreads();

    if (t < C) {
        const float* wr = fc2 + (size_t)t * J;
        float s = 0.f;
#pragma unroll
        for (int j = 0; j < J; j++) s += gcs[j] * wr[j];
        out[b * C + t] = 1.0f / (1.0f + expf(-s));
    }
}

// ---------------------------------------------------------------------------
extern "C" void kernel_launch(void* const* d_in, const int* in_sizes, int n_in,
                              void* d_out, int out_size)
{
    const float* x    = (const float*)d_in[0];
    const float* e    = (const float*)d_in[1];
    const float* w1   = (const float*)d_in[2];
    const float* w2   = (const float*)d_in[3];
    const float* fc1w = (const float*)d_in[4];
    const float* fc2w = (const float*)d_in[5];
    float* out = (float*)d_out;

    int n    = in_sizes[0] / (C * HW);   // 64
    int rows = n * C;                    // 32768

    float *avg, *B;
    cudaGetSymbolAddress((void**)&avg, g_avg);
    cudaGetSymbolAddress((void**)&B,  g_B);

    precompute_B_kernel<<<J, 512>>>(e, fc1w, w2, w1, B);

    int grid1 = (rows + 7) / 8;          // 8 warps per 256-thread block
    mean_pool_kernel<<<grid1, 256>>>(x, avg, rows);

    final_kernel<<<n, 544>>>(B, fc2w, out);
}

// round 7
// speedup vs baseline: 1.1286x; 1.1286x over previous
#include <cuda_runtime.h>
#include <cuda_bf16.h>
#include <math.h>

// ---------------------------------------------------------------------------
// CGCA branch, fully collapsed:
//   gc = adj·fc1·blockdiag(w2)·w1·avg = B·avg   (everything before relu is
//   linear & batch-independent except avg).
// Kernel 1 (fused): blocks 0..16 build B[17,512]; blocks 17.. do the spatial
//   mean x[n,512,56,56] -> g_avg[n,512]. The latency-bound precompute hides
//   entirely under the HBM-bound pool (both start in wave 1).
// Kernel 2: per-batch: gc = B·avg, relu, out = sigmoid(fc2·gc).
// ---------------------------------------------------------------------------

#define J   17
#define C   512
#define CA  272
#define HW  3136           // 56*56
#define HW4 784            // HW/4
#define NEG (-9e15f)

// flatnonzero(ADJ) — 49 entries
__constant__ int NZ[49] = {
      0,   1,
     17,  18,  19,
     35,  36,  40,
     54,  55,  57,
     71,  72,  73,
     89,  90,
    104, 105, 108, 109,
    125, 126, 127,
    143, 144, 147, 148, 152,
    162, 169,
    180, 181,
    197, 198, 199,
    212, 215, 216,
    229, 234, 235,
    251, 252, 253,
    269, 270,
    280, 281, 288
};

// scratch (static device globals — no allocation)
__device__ float g_avg[256 * C];   // pooled features, max batch 256
__device__ float g_B[J * C];       // collapsed linear map [17, 512]

// ---------------------------------------------------------------------------
// Fused kernel. 256 threads/block.
//   blockIdx.x <  J      : precompute branch — row j of B.
//   blockIdx.x >= J      : pool branch — 8 warps, one (n,c) row each.
// __launch_bounds__(256,4): regs<=64 (precompute load batching) while keeping
// >=32 warps/SM for the bandwidth-bound pool branch.
// ---------------------------------------------------------------------------
__global__ __launch_bounds__(256, 4) void fused_pool_precompute_kernel(
    const float* __restrict__ x,     // [n*C*HW]
    const float* __restrict__ e,     // [49]
    const float* __restrict__ fc1,   // [J, CA]
    const float* __restrict__ w2,    // [CA, J]  (blockdiag groups [16,J,J])
    const float* __restrict__ w1,    // [CA, C]
    float* __restrict__ avg,         // [n*C]
    float* __restrict__ B,           // [J, C]
    int rows)
{
    __shared__ float adjs[J * J];
    __shared__ float arow[J];
    __shared__ float F[CA];
    __shared__ float T[CA];

    const int t = threadIdx.x;

    if (blockIdx.x < J) {
        // ---------------- precompute branch: row j of B ----------------
        const int j = blockIdx.x;

        if (t < J * J) adjs[t] = NEG;
        __syncthreads();
        if (t < 49) adjs[NZ[t]] = e[t];
        __syncthreads();

        if (t == 0) {
            float m = NEG;
#pragma unroll
            for (int k = 0; k < J; k++) m = fmaxf(m, adjs[j * J + k]);
            float s = 0.f, tmp[J];
#pragma unroll
            for (int k = 0; k < J; k++) { tmp[k] = expf(adjs[j * J + k] - m); s += tmp[k]; }
            float inv = 1.0f / s;
#pragma unroll
            for (int k = 0; k < J; k++) arow[k] = tmp[k] * inv;
        }
        __syncthreads();

        // F[k] = sum_{j2} arow[j2] * fc1[j2, k]
        for (int idx = t; idx < CA; idx += 256) {
            float s = 0.f;
#pragma unroll
            for (int j2 = 0; j2 < J; j2++) s += arow[j2] * fc1[j2 * CA + idx];
            F[idx] = s;
        }
        __syncthreads();

        // T[g*17+i] = sum_o F[g*17+o] * w2[(g*17+o)*17 + i]
        for (int idx = t; idx < CA; idx += 256) {
            int g = idx / J, i = idx % J;
            float s = 0.f;
#pragma unroll
            for (int o = 0; o < J; o++) s += F[g * J + o] * w2[(g * J + o) * J + i];
            T[idx] = s;
        }
        __syncthreads();

        // B[j, c] = sum_k T[k] * w1[k, c] — each thread covers c = t, t+256.
        // Two independent chains x 4 accumulators each -> high MLP.
        {
            float a0 = 0.f, a1 = 0.f, a2 = 0.f, a3 = 0.f;
            float b0 = 0.f, b1 = 0.f, b2 = 0.f, b3 = 0.f;
#pragma unroll
            for (int k = 0; k < CA / 4; k++) {
                const float* r0 = w1 + (4 * k + 0) * C;
                const float* r1 = w1 + (4 * k + 1) * C;
                const float* r2 = w1 + (4 * k + 2) * C;
                const float* r3 = w1 + (4 * k + 3) * C;
                a0 += T[4 * k + 0] * r0[t];
                a1 += T[4 * k + 1] * r1[t];
                a2 += T[4 * k + 2] * r2[t];
                a3 += T[4 * k + 3] * r3[t];
                b0 += T[4 * k + 0] * r0[t + 256];
                b1 += T[4 * k + 1] * r1[t + 256];
                b2 += T[4 * k + 2] * r2[t + 256];
                b3 += T[4 * k + 3] * r3[t + 256];
            }
            B[j * C + t]       = (a0 + a1) + (a2 + a3);
            B[j * C + t + 256] = (b0 + b1) + (b2 + b3);
        }
    } else {
        // ---------------- pool branch: 8 warps, one (n,c) row each ------
        int warp = ((blockIdx.x - J) * 256 + t) >> 5;
        int lane = t & 31;
        if (warp >= rows) return;

        const float4* p = reinterpret_cast<const float4*>(x) + (size_t)warp * HW4;

        float4 a = make_float4(0.f, 0.f, 0.f, 0.f);
#pragma unroll
        for (int i = 0; i < 24; i++) {
            float4 v = __ldcs(&p[lane + i * 32]);
            a.x += v.x; a.y += v.y; a.z += v.z; a.w += v.w;
        }
        if (lane < 16) {                   // 784 - 24*32 = 16 tail vec4s
            float4 v = __ldcs(&p[768 + lane]);
            a.x += v.x; a.y += v.y; a.z += v.z; a.w += v.w;
        }
        float s = (a.x + a.y) + (a.z + a.w);
#pragma unroll
        for (int o = 16; o; o >>= 1) s += __shfl_xor_sync(0xffffffffu, s, o);

        if (lane == 0) avg[warp] = s * (1.0f / (float)HW);
    }
}

// ---------------------------------------------------------------------------
// Kernel 2: one block (544 threads = 17 warps) per batch element.
//   warp j:  gc[j] = relu( dot(B[j,:], avg) )
//   thread c<512: out[c] = sigmoid( dot(gc, fc2[c,:]) )
// ---------------------------------------------------------------------------
__global__ __launch_bounds__(544) void final_kernel(
    const float* __restrict__ B,     // [J, C]
    const float* __restrict__ fc2,   // [C, J]
    float* __restrict__ out)         // [n, C]
{
    __shared__ float avgs[C];
    __shared__ float gcs[J];

    const int b    = blockIdx.x;
    const int t    = threadIdx.x;
    const int wid  = t >> 5;       // 0..16
    const int lane = t & 31;

    if (t < C) avgs[t] = g_avg[b * C + t];
    __syncthreads();

    // 17 warps, one gc each
    {
        const float* wr = B + (size_t)wid * C;
        float s = 0.f;
#pragma unroll
        for (int k = lane; k < C; k += 32) s += avgs[k] * wr[k];
#pragma unroll
        for (int off = 16; off; off >>= 1) s += __shfl_xor_sync(0xffffffffu, s, off);
        if (lane == 0) gcs[wid] = fmaxf(s, 0.f);
    }
    __syncthreads();

    if (t < C) {
        const float* wr = fc2 + (size_t)t * J;
        float s = 0.f;
#pragma unroll
        for (int j = 0; j < J; j++) s += gcs[j] * wr[j];
        out[b * C + t] = 1.0f / (1.0f + expf(-s));
    }
}

// ---------------------------------------------------------------------------
extern "C" void kernel_launch(void* const* d_in, const int* in_sizes, int n_in,
                              void* d_out, int out_size)
{
    const float* x    = (const float*)d_in[0];
    const float* e    = (const float*)d_in[1];
    const float* w1   = (const float*)d_in[2];
    const float* w2   = (const float*)d_in[3];
    const float* fc1w = (const float*)d_in[4];
    const float* fc2w = (const float*)d_in[5];
    float* out = (float*)d_out;

    int n    = in_sizes[0] / (C * HW);   // 64
    int rows = n * C;                    // 32768

    float *avg, *B;
    cudaGetSymbolAddress((void**)&avg, g_avg);
    cudaGetSymbolAddress((void**)&B,  g_B);

    int grid = J + (rows + 7) / 8;       // 17 precompute blocks + 4096 pool blocks
    fused_pool_precompute_kernel<<<grid, 256>>>(x, e, fc1w, w2, w1, avg, B, rows);

    final_kernel<<<n, 544>>>(B, fc2w, out);
}